// round 11
// baseline (speedup 1.0000x reference)
#include <cuda_runtime.h>
#include <math.h>

#define NN 2048
#define BB 8
#define FIN 16
#define TT 12
#define FOUT 32
#define CC 192   // FIN*TT

// Scratch (allocation-free rule: __device__ globals)
__device__ float g_S  [(size_t)NN*NN];     // supports (tf32-rounded)
__device__ float g_S2 [(size_t)NN*NN];     // 2 * S @ S (tf32-rounded)
__device__ float g_xtf[(size_t)BB*NN*CC];  // x tf32-rounded
__device__ float g_rhs1[(size_t)BB*NN*CC];
__device__ float g_rhs2[(size_t)BB*NN*CC];

// ---------------------------------------------------------------------------
// helpers
// ---------------------------------------------------------------------------
__device__ __forceinline__ float f2tf32(float x) {
    unsigned r;
    asm("cvt.rna.tf32.f32 %0, %1;" : "=r"(r) : "f"(x));
    return __uint_as_float(r);
}
__device__ __forceinline__ void mma8(float* c,
                                     unsigned a0, unsigned a1, unsigned a2, unsigned a3,
                                     unsigned b0, unsigned b1) {
    asm volatile(
        "mma.sync.aligned.m16n8k8.row.col.f32.tf32.tf32.f32 "
        "{%0,%1,%2,%3},{%4,%5,%6,%7},{%8,%9},{%0,%1,%2,%3};"
        : "+f"(c[0]), "+f"(c[1]), "+f"(c[2]), "+f"(c[3])
        : "r"(a0), "r"(a1), "r"(a2), "r"(a3), "r"(b0), "r"(b1));
}
__device__ __forceinline__ unsigned uldf(const float& f) { return __float_as_uint(f); }

__device__ __forceinline__ void cpa16(unsigned saddr, const void* gptr) {
    asm volatile("cp.async.cg.shared.global [%0], [%1], 16;" :: "r"(saddr), "l"(gptr));
}
__device__ __forceinline__ void cpa_commit() {
    asm volatile("cp.async.commit_group;" ::: "memory");
}
template<int N> __device__ __forceinline__ void cpa_wait() {
    asm volatile("cp.async.wait_group %0;" :: "n"(N) : "memory");
}

// ---------------------------------------------------------------------------
// Kernel 1: S = rowsoftmax(relu(E E^T)), stored tf32-rounded.
// ---------------------------------------------------------------------------
__global__ void __launch_bounds__(256) supports_kernel(const float* __restrict__ E) {
    int n = blockIdx.x;
    __shared__ float en[FIN];
    __shared__ float row[NN];
    __shared__ float red[256];
    int tid = threadIdx.x;
    if (tid < FIN) en[tid] = E[n*FIN + tid];
    __syncthreads();

    float lmax = 0.0f;
    for (int m = tid; m < NN; m += 256) {
        const float* em = E + m*FIN;
        float s = 0.f;
        #pragma unroll
        for (int f = 0; f < FIN; f++) s = fmaf(en[f], em[f], s);
        s = fmaxf(s, 0.f);
        row[m] = s;
        lmax = fmaxf(lmax, s);
    }
    red[tid] = lmax; __syncthreads();
    for (int s = 128; s > 0; s >>= 1) {
        if (tid < s) red[tid] = fmaxf(red[tid], red[tid+s]);
        __syncthreads();
    }
    float gmax = red[0];
    __syncthreads();

    float lsum = 0.f;
    for (int m = tid; m < NN; m += 256) {
        float e = expf(row[m] - gmax);
        row[m] = e;
        lsum += e;
    }
    red[tid] = lsum; __syncthreads();
    for (int s = 128; s > 0; s >>= 1) {
        if (tid < s) red[tid] += red[tid+s];
        __syncthreads();
    }
    float inv = 1.0f / red[0];
    for (int m = tid; m < NN; m += 256)
        g_S[(size_t)n*NN + m] = f2tf32(row[m] * inv);
}

// ---------------------------------------------------------------------------
// Kernel 1b: pre-round x to tf32.
// ---------------------------------------------------------------------------
__global__ void __launch_bounds__(256) xtf_kernel(const float* __restrict__ x) {
    int i = blockIdx.x * 256 + threadIdx.x;
    float4 v = ((const float4*)x)[i];
    v.x = f2tf32(v.x); v.y = f2tf32(v.y); v.z = f2tf32(v.z); v.w = f2tf32(v.w);
    ((float4*)g_xtf)[i] = v;
}

// ---------------------------------------------------------------------------
// Kernel 2: g_S2 = 2 * S @ S  (TF32, cp.async 2-stage)
// Block tile 64m x 128n, 256 thr = 8 warps (2m x 4n), warp tile 32x32, K16.
// Grid MUST be (NN/128, NN/64).
// ---------------------------------------------------------------------------
__global__ void __launch_bounds__(256) s2_gemm_tc3() {
    __shared__ __align__(16) float As[2][64][20];
    __shared__ __align__(16) float Bs[2][16][136];
    int tid  = threadIdx.x;
    int warp = tid >> 5, lane = tid & 31;
    int wm = warp >> 2, wn = warp & 3;          // 2 x 4
    int grp = lane >> 2, qid = lane & 3;
    int rowBase = blockIdx.y * 64, colBase = blockIdx.x * 128;

    float acc[2][4][4];
    #pragma unroll
    for (int i = 0; i < 2; i++)
        #pragma unroll
        for (int j = 0; j < 4; j++)
            #pragma unroll
            for (int q = 0; q < 4; q++) acc[i][j][q] = 0.f;

    // cp.async: A 256 chunks (1/thr), B 512 chunks (2/thr)
    int aRow = tid >> 2, aCk = tid & 3;
    int bRow0 = (tid*2) >> 5,   bCn0 = (tid*2) & 31;
    int bRow1 = (tid*2+1) >> 5, bCn1 = (tid*2+1) & 31;

#define S2_LOAD(st, p0)                                                              \
    do {                                                                             \
        cpa16((unsigned)__cvta_generic_to_shared(&As[st][aRow][aCk*4]),              \
              &g_S[(size_t)(rowBase+aRow)*NN + (p0) + aCk*4]);                       \
        cpa16((unsigned)__cvta_generic_to_shared(&Bs[st][bRow0][bCn0*4]),            \
              &g_S[(size_t)((p0)+bRow0)*NN + colBase + bCn0*4]);                     \
        cpa16((unsigned)__cvta_generic_to_shared(&Bs[st][bRow1][bCn1*4]),            \
              &g_S[(size_t)((p0)+bRow1)*NN + colBase + bCn1*4]);                     \
    } while (0)

    S2_LOAD(0, 0);
    cpa_commit();

    for (int it = 0; it < NN/16; it++) {
        int cur = it & 1;
        if (it < NN/16 - 1) S2_LOAD(cur ^ 1, (it + 1) * 16);
        cpa_commit();
        cpa_wait<1>();
        __syncthreads();

        #pragma unroll
        for (int ks = 0; ks < 16; ks += 8) {
            unsigned af[2][4], bf[4][2];
            #pragma unroll
            for (int i = 0; i < 2; i++) {
                int row = wm*32 + i*16 + grp;
                af[i][0] = uldf(As[cur][row  ][ks+qid  ]);
                af[i][1] = uldf(As[cur][row+8][ks+qid  ]);
                af[i][2] = uldf(As[cur][row  ][ks+qid+4]);
                af[i][3] = uldf(As[cur][row+8][ks+qid+4]);
            }
            #pragma unroll
            for (int j = 0; j < 4; j++) {
                int col = wn*32 + j*8 + grp;
                bf[j][0] = uldf(Bs[cur][ks+qid  ][col]);
                bf[j][1] = uldf(Bs[cur][ks+qid+4][col]);
            }
            #pragma unroll
            for (int i = 0; i < 2; i++)
                #pragma unroll
                for (int j = 0; j < 4; j++)
                    mma8(acc[i][j], af[i][0], af[i][1], af[i][2], af[i][3],
                         bf[j][0], bf[j][1]);
        }
        __syncthreads();
    }
#undef S2_LOAD

    #pragma unroll
    for (int i = 0; i < 2; i++) {
        #pragma unroll
        for (int j = 0; j < 4; j++) {
            int r = rowBase + wm*32 + i*16 + grp;
            int c = colBase + wn*32 + j*8 + qid*2;
            float2 v0 = make_float2(f2tf32(2.f*acc[i][j][0]), f2tf32(2.f*acc[i][j][1]));
            float2 v1 = make_float2(f2tf32(2.f*acc[i][j][2]), f2tf32(2.f*acc[i][j][3]));
            *(float2*)&g_S2[(size_t)r*NN + c]     = v0;
            *(float2*)&g_S2[(size_t)(r+8)*NN + c] = v1;
        }
    }
}

// ---------------------------------------------------------------------------
// Kernel 3: fused dual masked-GEMM (TF32, cp.async 2-stage).
// Block 32m x 192c, 256 thr = 8 warps (2m x 4c), warp tile 16x48, K16.
// acc = 48 floats/thread; __launch_bounds__(256,2) -> 2 blocks/SM.
// att streamed from DRAM exactly once. Mask multiply in A-fragment registers.
// ---------------------------------------------------------------------------
__global__ void __launch_bounds__(256, 2) fused_rhs_tc3(const float* __restrict__ att) {
    __shared__ __align__(16) float Ts[2][3][16][40];   // 0=S, 1=S2, 2=att : [n][m]
    __shared__ __align__(16) float Xs[2][16][200];     // [n][c]

    int tid  = threadIdx.x;
    int warp = tid >> 5, lane = tid & 31;
    int wm = warp >> 2, wn = warp & 3;          // 2 x 4
    int grp = lane >> 2, qid = lane & 3;
    int b  = blockIdx.y;
    int m0 = blockIdx.x * 32;

    const float* attB = att   + (size_t)b*NN*NN;
    const float* xB   = g_xtf + (size_t)b*NN*CC;

    float acc1[6][4], acc2[6][4];
    #pragma unroll
    for (int j = 0; j < 6; j++)
        #pragma unroll
        for (int q = 0; q < 4; q++) { acc1[j][q] = 0.f; acc2[j][q] = 0.f; }

    // cp.async: Ts 3 mats x 16 rows x 8 chunks = 384 (threads 0..127, 3 each);
    //           Xs 16 x 48 = 768 chunks (all 256 threads, 3 each)

#define F_LOAD(st, n0)                                                                 \
    do {                                                                               \
        if (tid < 128) {                                                               \
            _Pragma("unroll")                                                          \
            for (int r = 0; r < 3; r++) {                                              \
                int ca = tid*3 + r;                                                    \
                int mat = ca >> 7, rem = ca & 127;                                     \
                int row = rem >> 3, cm = rem & 7;                                      \
                const float* src = (mat == 0) ? g_S : (mat == 1) ? g_S2 : attB;        \
                cpa16((unsigned)__cvta_generic_to_shared(&Ts[st][mat][row][cm*4]),     \
                      src + (size_t)((n0)+row)*NN + m0 + cm*4);                        \
            }                                                                          \
        }                                                                              \
        _Pragma("unroll")                                                              \
        for (int r = 0; r < 3; r++) {                                                  \
            int cx = tid*3 + r;                                                        \
            int row = cx / 48, cc = cx % 48;                                           \
            cpa16((unsigned)__cvta_generic_to_shared(&Xs[st][row][cc*4]),              \
                  xB + (size_t)((n0)+row)*CC + cc*4);                                  \
        }                                                                              \
    } while (0)

    F_LOAD(0, 0);
    cpa_commit();

    for (int it = 0; it < NN/16; it++) {
        int cur = it & 1;
        if (it < NN/16 - 1) F_LOAD(cur ^ 1, (it + 1) * 16);
        cpa_commit();
        cpa_wait<1>();
        __syncthreads();

        #pragma unroll
        for (int ks = 0; ks < 16; ks += 8) {
            int row = wm*16 + grp;
            float s0  = Ts[cur][0][ks+qid  ][row],  s1  = Ts[cur][0][ks+qid  ][row+8];
            float s2_ = Ts[cur][0][ks+qid+4][row],  s3  = Ts[cur][0][ks+qid+4][row+8];
            float u0  = Ts[cur][1][ks+qid  ][row],  u1  = Ts[cur][1][ks+qid  ][row+8];
            float u2  = Ts[cur][1][ks+qid+4][row],  u3  = Ts[cur][1][ks+qid+4][row+8];
            float a0  = Ts[cur][2][ks+qid  ][row],  a1  = Ts[cur][2][ks+qid  ][row+8];
            float a2  = Ts[cur][2][ks+qid+4][row],  a3  = Ts[cur][2][ks+qid+4][row+8];
            unsigned w1f[4], w2f[4];
            w1f[0] = uldf(f2tf32(s0 *a0)); w1f[1] = uldf(f2tf32(s1 *a1));
            w1f[2] = uldf(f2tf32(s2_*a2)); w1f[3] = uldf(f2tf32(s3 *a3));
            w2f[0] = uldf(f2tf32(u0 *a0)); w2f[1] = uldf(f2tf32(u1 *a1));
            w2f[2] = uldf(f2tf32(u2 *a2)); w2f[3] = uldf(f2tf32(u3 *a3));
            #pragma unroll
            for (int j = 0; j < 6; j++) {
                int col = wn*48 + j*8 + grp;
                unsigned b0 = uldf(Xs[cur][ks+qid  ][col]);
                unsigned b1 = uldf(Xs[cur][ks+qid+4][col]);
                mma8(acc1[j], w1f[0], w1f[1], w1f[2], w1f[3], b0, b1);
                mma8(acc2[j], w2f[0], w2f[1], w2f[2], w2f[3], b0, b1);
            }
        }
        __syncthreads();
    }
#undef F_LOAD

    #pragma unroll
    for (int j = 0; j < 6; j++) {
        int r = m0 + wm*16 + grp;
        int c = wn*48 + j*8 + qid*2;
        size_t base = ((size_t)b*NN + r)*CC + c;
        *(float2*)&g_rhs1[base]        = make_float2(acc1[j][0], acc1[j][1]);
        *(float2*)&g_rhs1[base + 8*CC] = make_float2(acc1[j][2], acc1[j][3]);
        *(float2*)&g_rhs2[base]        = make_float2(acc2[j][0], acc2[j][1]);
        *(float2*)&g_rhs2[base + 8*CC] = make_float2(acc2[j][2], acc2[j][3]);
    }
}

// ---------------------------------------------------------------------------
// Kernel 4: epilogue (unchanged).
// ---------------------------------------------------------------------------
#define EROWS 16
__global__ void __launch_bounds__(384) epilogue2_kernel(const float* __restrict__ att,
                                                        const float* __restrict__ x,
                                                        const float* __restrict__ theta,
                                                        float* __restrict__ out) {
    __shared__ float r1[EROWS*CC], r2[EROWS*CC], xs[EROWS*CC];
    __shared__ float ds[EROWS];
    int blk = blockIdx.x;
    int tid = threadIdx.x;
    size_t base = (size_t)blk * EROWS * CC;

    #pragma unroll
    for (int r = 0; r < 2; r++) {
        int idx = tid + r*384;
        *(float4*)&r1[idx*4] = *(const float4*)&g_rhs1[base + (size_t)idx*4];
        *(float4*)&r2[idx*4] = *(const float4*)&g_rhs2[base + (size_t)idx*4];
        *(float4*)&xs[idx*4] = *(const float4*)&x[base + (size_t)idx*4];
    }
    if (tid < EROWS) {
        int bm = blk*EROWS + tid;
        int b = bm >> 11;
        int m = bm & (NN - 1);
        ds[tid] = att[(size_t)b*NN*NN + (size_t)m*NN + m];
    }
    int o = tid / TT;
    int t = tid - o*TT;
    float th1[FIN], th2[FIN], th0m2[FIN];
    #pragma unroll
    for (int f = 0; f < FIN; f++) {
        float t0 = theta[              f*FOUT + o];
        float t1 = theta[  FIN*FOUT + f*FOUT + o];
        float t2 = theta[2*FIN*FOUT + f*FOUT + o];
        th1[f] = t1; th2[f] = t2; th0m2[f] = t0 - t2;
    }
    __syncthreads();

    size_t outBase = (size_t)blk * EROWS * (FOUT*TT);
    #pragma unroll 4
    for (int row = 0; row < EROWS; row++) {
        float d = ds[row];
        const float* R1 = r1 + row*CC;
        const float* R2 = r2 + row*CC;
        const float* X  = xs + row*CC;
        float acc = 0.f;
        #pragma unroll
        for (int f = 0; f < FIN; f++) {
            int c = f*TT + t;
            acc = fmaf(R1[c], th1[f], acc);
            acc = fmaf(R2[c], th2[f], acc);
            acc = fmaf(d * X[c], th0m2[f], acc);
        }
        out[outBase + row*(FOUT*TT) + tid] = fmaxf(acc, 0.f);
    }
}

// ---------------------------------------------------------------------------
extern "C" void kernel_launch(void* const* d_in, const int* in_sizes, int n_in,
                              void* d_out, int out_size) {
    const float* x = nullptr;
    const float* att = nullptr;
    const float* emb = nullptr;
    const float* theta = nullptr;
    for (int i = 0; i < n_in; i++) {
        switch (in_sizes[i]) {
            case BB*NN*FIN*TT:   x     = (const float*)d_in[i]; break;
            case BB*NN*NN:       att   = (const float*)d_in[i]; break;
            case NN*FIN:         emb   = (const float*)d_in[i]; break;
            case 3*FIN*FOUT:     theta = (const float*)d_in[i]; break;
            default: break;
        }
    }
    float* out = (float*)d_out;

    supports_kernel<<<NN, 256>>>(emb);
    xtf_kernel<<<BB*NN*CC/4/256, 256>>>(x);
    s2_gemm_tc3<<<dim3(NN/128, NN/64), 256>>>();   // FIXED: 64-row tile -> NN/64 blocks in y
    fused_rhs_tc3<<<dim3(NN/32, BB), 256>>>(att);
    epilogue2_kernel<<<BB*NN/EROWS, 384>>>(att, x, theta, out);
}